// round 1
// baseline (speedup 1.0000x reference)
#include <cuda_runtime.h>
#include <math_constants.h>
#include <math.h>

#define D_MODEL   768
#define NUM_HEADS 12
#define HEAD_DIM  64
#define BATCH     4
#define SEQ       1024
#define NTOK      (BATCH*SEQ)
#define LOG2E     1.4426950408889634f

// ---------------- scratch (static device allocations are allowed) -----------
__device__ float g_Q[NTOK * D_MODEL];     // [b,h,s,d]
__device__ float g_K[NTOK * D_MODEL];     // [b,h,s,d]
__device__ float g_V[NTOK * D_MODEL];     // [b,h,s,d]
__device__ float g_att[NTOK * D_MODEL];   // [b,s, h*64+d] flat [4096,768]
__device__ float g_cx[NTOK];
__device__ float g_cy[NTOK];

// ---------------- box centers ----------------------------------------------
__global__ void centers_kernel(const float* __restrict__ boxes) {
    int i = blockIdx.x * blockDim.x + threadIdx.x;
    if (i < NTOK) {
        float4 bx = *(const float4*)(boxes + (size_t)i * 4);
        g_cx[i] = (bx.x + bx.z) * 0.5f;
        g_cy[i] = (bx.y + bx.w) * 0.5f;
    }
}

// ---------------- fp32 tiled GEMM:  out[n,o] = sum_d A[n,d]*W[o,d] + bias[o]
// LAYOUT 1: scatter into [b,h,s,d];  LAYOUT 0: flat [n, D_MODEL]
template<int LAYOUT>
__global__ __launch_bounds__(256) void gemm_kernel(
    const float* __restrict__ A, const float* __restrict__ W,
    const float* __restrict__ bias, float* __restrict__ out)
{
    __shared__ float As[8][132];
    __shared__ float Ws[8][132];
    const int t  = threadIdx.x;
    const int tx = t & 15, ty = t >> 4;
    const int row0 = blockIdx.y * 128;
    const int col0 = blockIdx.x * 128;
    const int lr = t >> 1;
    const int lk = (t & 1) * 4;
    const float* Ap = A + (size_t)(row0 + lr) * D_MODEL + lk;
    const float* Wp = W + (size_t)(col0 + lr) * D_MODEL + lk;

    float acc[8][8];
#pragma unroll
    for (int i = 0; i < 8; i++)
#pragma unroll
        for (int j = 0; j < 8; j++) acc[i][j] = 0.f;

    for (int k0 = 0; k0 < D_MODEL; k0 += 8) {
        float4 av = *(const float4*)(Ap + k0);
        float4 wv = *(const float4*)(Wp + k0);
        As[lk+0][lr] = av.x; As[lk+1][lr] = av.y; As[lk+2][lr] = av.z; As[lk+3][lr] = av.w;
        Ws[lk+0][lr] = wv.x; Ws[lk+1][lr] = wv.y; Ws[lk+2][lr] = wv.z; Ws[lk+3][lr] = wv.w;
        __syncthreads();
#pragma unroll
        for (int k = 0; k < 8; k++) {
            float4 a0 = *(const float4*)&As[k][ty*8];
            float4 a1 = *(const float4*)&As[k][ty*8 + 4];
            float4 b0 = *(const float4*)&Ws[k][tx*8];
            float4 b1 = *(const float4*)&Ws[k][tx*8 + 4];
            float ar[8] = {a0.x,a0.y,a0.z,a0.w,a1.x,a1.y,a1.z,a1.w};
            float br[8] = {b0.x,b0.y,b0.z,b0.w,b1.x,b1.y,b1.z,b1.w};
#pragma unroll
            for (int i = 0; i < 8; i++)
#pragma unroll
                for (int j = 0; j < 8; j++) acc[i][j] += ar[i] * br[j];
        }
        __syncthreads();
    }

    const int colb = col0 + tx * 8;
    float bsv[8];
#pragma unroll
    for (int j = 0; j < 8; j++) bsv[j] = bias[colb + j];

#pragma unroll
    for (int i = 0; i < 8; i++) {
        int n = row0 + ty * 8 + i;
        float r[8];
#pragma unroll
        for (int j = 0; j < 8; j++) r[j] = acc[i][j] + bsv[j];
        size_t base;
        if (LAYOUT == 1) {
            int b = n >> 10, s = n & 1023;
            int h = colb >> 6, d0 = colb & 63;
            base = (((size_t)(b * NUM_HEADS + h)) * SEQ + s) * HEAD_DIM + d0;
        } else {
            base = (size_t)n * D_MODEL + colb;
        }
        *(float4*)(out + base)     = make_float4(r[0], r[1], r[2], r[3]);
        *(float4*)(out + base + 4) = make_float4(r[4], r[5], r[6], r[7]);
    }
}

// ---------------- fused flash attention with spatial bias -------------------
// grid: (SEQ/128, BATCH*NUM_HEADS), 256 threads, ~134KB dynamic smem
__global__ __launch_bounds__(256) void attn_kernel(const float* __restrict__ sbias)
{
    extern __shared__ float sm[];
    float* Qs  = sm;                    // [64][128]  (d-major, transposed)
    float* KV  = sm + 64 * 128;         // K view [64][128] / V view [128][68]
    float* Ps  = KV + 8704;             // [128][132]
    float* qcx = Ps + 128 * 132;
    float* qcy = qcx + 128;
    float* kcx = qcy + 128;
    float* kcy = kcx + 128;

    const int t  = threadIdx.x;
    const int tx = t & 15, ty = t >> 4;
    const int bh = blockIdx.y;
    const int b  = bh / NUM_HEADS, h = bh % NUM_HEADS;
    const int q0 = blockIdx.x * 128;
    const float sb = sbias[h];
    const size_t headbase = (size_t)bh * SEQ * HEAD_DIM;

    // load Q tile transposed: Qs[d][r]
    {
        int r = t >> 1;
        int dbase = (t & 1) * 32;
        const float* qp = g_Q + headbase + (size_t)(q0 + r) * HEAD_DIM + dbase;
#pragma unroll
        for (int u = 0; u < 8; u++) {
            float4 v = *(const float4*)(qp + u * 4);
            int d = dbase + u * 4;
            Qs[(d+0)*128 + r] = v.x;
            Qs[(d+1)*128 + r] = v.y;
            Qs[(d+2)*128 + r] = v.z;
            Qs[(d+3)*128 + r] = v.w;
        }
    }
    if (t < 128) {
        qcx[t] = g_cx[b * SEQ + q0 + t];
        qcy[t] = g_cy[b * SEQ + q0 + t];
    }

    float m[8], l[8], acc[8][4];
#pragma unroll
    for (int i = 0; i < 8; i++) {
        m[i] = -CUDART_INF_F; l[i] = 0.f;
#pragma unroll
        for (int j = 0; j < 4; j++) acc[i][j] = 0.f;
    }
    float qx[8], qy[8];

    for (int kt = 0; kt < SEQ / 128; kt++) {
        const int k0 = kt * 128;
        // load K tile transposed into KV: K[d][c]
        {
            int r = t >> 1;
            int dbase = (t & 1) * 32;
            const float* kp = g_K + headbase + (size_t)(k0 + r) * HEAD_DIM + dbase;
#pragma unroll
            for (int u = 0; u < 8; u++) {
                float4 v = *(const float4*)(kp + u * 4);
                int d = dbase + u * 4;
                KV[(d+0)*128 + r] = v.x;
                KV[(d+1)*128 + r] = v.y;
                KV[(d+2)*128 + r] = v.z;
                KV[(d+3)*128 + r] = v.w;
            }
        }
        if (t < 128) {
            kcx[t] = g_cx[b * SEQ + k0 + t];
            kcy[t] = g_cy[b * SEQ + k0 + t];
        }
        __syncthreads();
        if (kt == 0) {
#pragma unroll
            for (int i = 0; i < 8; i++) { qx[i] = qcx[ty*8+i]; qy[i] = qcy[ty*8+i]; }
        }

        // ---- scores: S[r][c] = sum_d Q[r,d]*K[c,d]
        float sc[8][8];
#pragma unroll
        for (int i = 0; i < 8; i++)
#pragma unroll
            for (int j = 0; j < 8; j++) sc[i][j] = 0.f;

#pragma unroll 4
        for (int d = 0; d < 64; d++) {
            float4 a0 = *(const float4*)&Qs[d*128 + ty*8];
            float4 a1 = *(const float4*)&Qs[d*128 + ty*8 + 4];
            float4 b0 = *(const float4*)&KV[d*128 + tx*8];
            float4 b1 = *(const float4*)&KV[d*128 + tx*8 + 4];
            float ar[8] = {a0.x,a0.y,a0.z,a0.w,a1.x,a1.y,a1.z,a1.w};
            float br[8] = {b0.x,b0.y,b0.z,b0.w,b1.x,b1.y,b1.z,b1.w};
#pragma unroll
            for (int i = 0; i < 8; i++)
#pragma unroll
                for (int j = 0; j < 8; j++) sc[i][j] += ar[i] * br[j];
        }

        // ---- spatial bias + scale, move to exp2 domain
        float kx[8], ky[8];
#pragma unroll
        for (int j = 0; j < 8; j++) { kx[j] = kcx[tx*8+j]; ky[j] = kcy[tx*8+j]; }
#pragma unroll
        for (int i = 0; i < 8; i++)
#pragma unroll
            for (int j = 0; j < 8; j++) {
                float dx = qx[i] - kx[j], dy = qy[i] - ky[j];
                float dist = sqrtf(dx*dx + dy*dy);
                sc[i][j] = (sc[i][j] * 0.125f - dist * sb) * LOG2E;
            }

        // ---- online softmax (16 lanes share each row group)
#pragma unroll
        for (int i = 0; i < 8; i++) {
            float v = sc[i][0];
#pragma unroll
            for (int j = 1; j < 8; j++) v = fmaxf(v, sc[i][j]);
            v = fmaxf(v, __shfl_xor_sync(0xffffffffu, v, 1));
            v = fmaxf(v, __shfl_xor_sync(0xffffffffu, v, 2));
            v = fmaxf(v, __shfl_xor_sync(0xffffffffu, v, 4));
            v = fmaxf(v, __shfl_xor_sync(0xffffffffu, v, 8));
            float mnew = fmaxf(m[i], v);
            float scale = exp2f(m[i] - mnew);
            m[i] = mnew;
            float s = 0.f;
#pragma unroll
            for (int j = 0; j < 8; j++) {
                float p = exp2f(sc[i][j] - mnew);
                sc[i][j] = p;
                s += p;
            }
            s += __shfl_xor_sync(0xffffffffu, s, 1);
            s += __shfl_xor_sync(0xffffffffu, s, 2);
            s += __shfl_xor_sync(0xffffffffu, s, 4);
            s += __shfl_xor_sync(0xffffffffu, s, 8);
            l[i] = l[i] * scale + s;
#pragma unroll
            for (int jd = 0; jd < 4; jd++) acc[i][jd] *= scale;
        }

        // ---- stage P
#pragma unroll
        for (int i = 0; i < 8; i++) {
            int r = ty * 8 + i;
            *(float4*)&Ps[r*132 + tx*8]     = make_float4(sc[i][0], sc[i][1], sc[i][2], sc[i][3]);
            *(float4*)&Ps[r*132 + tx*8 + 4] = make_float4(sc[i][4], sc[i][5], sc[i][6], sc[i][7]);
        }
        __syncthreads();   // K reads done + P visible before V overwrites KV

        // ---- load V: V[c][d] padded to 68
        {
            int c = t >> 1;
            int dbase = (t & 1) * 32;
            const float* vp = g_V + headbase + (size_t)(k0 + c) * HEAD_DIM + dbase;
#pragma unroll
            for (int u = 0; u < 8; u++)
                *(float4*)&KV[c*68 + dbase + u*4] = *(const float4*)(vp + u*4);
        }
        __syncthreads();

        // ---- O += P @ V  (rows ty*8..+7, dims tx*4..+3)
#pragma unroll 1
        for (int cc = 0; cc < 32; cc++) {
            int c4 = cc * 4;
            float4 pv[8];
#pragma unroll
            for (int i = 0; i < 8; i++) pv[i] = *(const float4*)&Ps[(ty*8+i)*132 + c4];
            float4 vv[4];
#pragma unroll
            for (int u = 0; u < 4; u++) vv[u] = *(const float4*)&KV[(c4+u)*68 + tx*4];
#pragma unroll
            for (int i = 0; i < 8; i++) {
                acc[i][0] += pv[i].x*vv[0].x + pv[i].y*vv[1].x + pv[i].z*vv[2].x + pv[i].w*vv[3].x;
                acc[i][1] += pv[i].x*vv[0].y + pv[i].y*vv[1].y + pv[i].z*vv[2].y + pv[i].w*vv[3].y;
                acc[i][2] += pv[i].x*vv[0].z + pv[i].y*vv[1].z + pv[i].z*vv[2].z + pv[i].w*vv[3].z;
                acc[i][3] += pv[i].x*vv[0].w + pv[i].y*vv[1].w + pv[i].z*vv[2].w + pv[i].w*vv[3].w;
            }
        }
        __syncthreads();   // before next iter overwrites KV / kc
    }

    // ---- finalize: write [b, s, h*64+d] flat
#pragma unroll
    for (int i = 0; i < 8; i++) {
        int r = q0 + ty * 8 + i;
        float inv = 1.f / l[i];
        size_t base = ((size_t)(b * SEQ + r)) * D_MODEL + h * HEAD_DIM + tx * 4;
        *(float4*)(g_att + base) = make_float4(acc[i][0]*inv, acc[i][1]*inv,
                                               acc[i][2]*inv, acc[i][3]*inv);
    }
}

// ---------------- launch ----------------------------------------------------
extern "C" void kernel_launch(void* const* d_in, const int* in_sizes, int n_in,
                              void* d_out, int out_size)
{
    const float* x     = (const float*)d_in[0];
    const float* boxes = (const float*)d_in[1];
    const float* Wq    = (const float*)d_in[2];
    const float* bq    = (const float*)d_in[3];
    const float* Wk    = (const float*)d_in[4];
    const float* bk    = (const float*)d_in[5];
    const float* Wv    = (const float*)d_in[6];
    const float* bv    = (const float*)d_in[7];
    const float* Wo    = (const float*)d_in[8];
    const float* bo    = (const float*)d_in[9];
    const float* sbias = (const float*)d_in[10];
    float* out = (float*)d_out;

    float *pQ, *pK, *pV, *pAtt;
    cudaGetSymbolAddress((void**)&pQ,   g_Q);
    cudaGetSymbolAddress((void**)&pK,   g_K);
    cudaGetSymbolAddress((void**)&pV,   g_V);
    cudaGetSymbolAddress((void**)&pAtt, g_att);

    const int ATTN_SMEM = (64*128 + 8704 + 128*132 + 4*128) * 4;  // 137216 B
    cudaFuncSetAttribute(attn_kernel, cudaFuncAttributeMaxDynamicSharedMemorySize, ATTN_SMEM);

    centers_kernel<<<(NTOK + 255) / 256, 256>>>(boxes);

    dim3 ggrid(D_MODEL / 128, NTOK / 128);   // (6, 32)
    gemm_kernel<1><<<ggrid, 256>>>(x, Wq, bq, pQ);
    gemm_kernel<1><<<ggrid, 256>>>(x, Wk, bk, pK);
    gemm_kernel<1><<<ggrid, 256>>>(x, Wv, bv, pV);

    dim3 agrid(SEQ / 128, BATCH * NUM_HEADS); // (8, 48)
    attn_kernel<<<agrid, 256, ATTN_SMEM>>>(sbias);

    gemm_kernel<0><<<ggrid, 256>>>(pAtt, Wo, bo, out);
}

// round 3
// speedup vs baseline: 1.3591x; 1.3591x over previous
#include <cuda_runtime.h>
#include <math_constants.h>
#include <math.h>
#include <stdint.h>

#define D_MODEL   768
#define NUM_HEADS 12
#define HEAD_DIM  64
#define BATCH     4
#define SEQ       1024
#define NTOK      (BATCH*SEQ)
#define LOG2E     1.4426950408889634f

// ---------------- scratch ----------------------------------------------------
__device__ float g_Q[NTOK * D_MODEL];     // [b,h,s,d]
__device__ float g_K[NTOK * D_MODEL];     // [b,h,s,d]
__device__ float g_V[NTOK * D_MODEL];     // [b,h,s,d]
__device__ float g_att[NTOK * D_MODEL];   // [b,s, h*64+d] flat [4096,768]
__device__ float g_cx[NTOK];
__device__ float g_cy[NTOK];

// ---------------- box centers ----------------------------------------------
__global__ void centers_kernel(const float* __restrict__ boxes) {
    int i = blockIdx.x * blockDim.x + threadIdx.x;
    if (i < NTOK) {
        float4 bx = *(const float4*)(boxes + (size_t)i * 4);
        g_cx[i] = (bx.x + bx.z) * 0.5f;
        g_cy[i] = (bx.y + bx.w) * 0.5f;
    }
}

// ---------------- tf32 helpers ----------------------------------------------
// cvt.rna.tf32.f32 writes a .b32 destination (uint32 reg), not .f32
__device__ __forceinline__ uint32_t to_tf32(float x) {
    uint32_t r;
    asm("cvt.rna.tf32.f32 %0, %1;" : "=r"(r) : "f"(x));
    return r;
}

__device__ __forceinline__ void mma_tf32(float* c, uint32_t a0, uint32_t a1,
                                         uint32_t a2, uint32_t a3,
                                         uint32_t b0, uint32_t b1) {
    asm volatile(
        "mma.sync.aligned.m16n8k8.row.col.f32.tf32.tf32.f32 "
        "{%0,%1,%2,%3}, {%4,%5,%6,%7}, {%8,%9}, {%0,%1,%2,%3};\n"
        : "+f"(c[0]), "+f"(c[1]), "+f"(c[2]), "+f"(c[3])
        : "r"(a0), "r"(a1), "r"(a2), "r"(a3), "r"(b0), "r"(b1));
}

// ---------------- TF32 tensor-core GEMM: out[n,o] = A[n,:] . W[o,:] + bias[o]
// BM=BN=128, BK=16, 256 threads, warps 2(m) x 4(n), each warp 64x32 via
// 4x4 m16n8k8 tiles. Smem staged k-major [k][m] stride 132 (conflict-free
// fragment loads), tf32-converted at staging. Double buffered.
// LAYOUT 1: scatter into [b,h,s,d]; LAYOUT 0: flat [n, D_MODEL]
template<int LAYOUT>
__global__ __launch_bounds__(256) void gemm_tc_kernel(
    const float* __restrict__ A, const float* __restrict__ W,
    const float* __restrict__ bias, float* __restrict__ out)
{
    __shared__ uint32_t As[2][16][132];
    __shared__ uint32_t Ws[2][16][132];

    const int t    = threadIdx.x;
    const int lane = t & 31;
    const int warp = t >> 5;
    const int wm   = warp & 1;        // 0..1
    const int wn   = warp >> 1;       // 0..3
    const int row0 = blockIdx.y * 128;
    const int col0 = blockIdx.x * 128;

    // staging mapping: m = t>>1 (0..127), k0 = (t&1)*8
    const int sm_m  = t >> 1;
    const int sm_k0 = (t & 1) * 8;
    const float* Ap = A + (size_t)(row0 + sm_m) * D_MODEL + sm_k0;
    const float* Wp = W + (size_t)(col0 + sm_m) * D_MODEL + sm_k0;

    float acc[4][4][4];
#pragma unroll
    for (int mt = 0; mt < 4; mt++)
#pragma unroll
        for (int nt = 0; nt < 4; nt++)
#pragma unroll
            for (int r = 0; r < 4; r++) acc[mt][nt][r] = 0.f;

    // prefetch tile 0
    float4 a0v = *(const float4*)(Ap);
    float4 a1v = *(const float4*)(Ap + 4);
    float4 w0v = *(const float4*)(Wp);
    float4 w1v = *(const float4*)(Wp + 4);
    {
        float av[8] = {a0v.x,a0v.y,a0v.z,a0v.w,a1v.x,a1v.y,a1v.z,a1v.w};
        float wv[8] = {w0v.x,w0v.y,w0v.z,w0v.w,w1v.x,w1v.y,w1v.z,w1v.w};
#pragma unroll
        for (int j = 0; j < 8; j++) {
            As[0][sm_k0 + j][sm_m] = to_tf32(av[j]);
            Ws[0][sm_k0 + j][sm_m] = to_tf32(wv[j]);
        }
    }
    __syncthreads();

    const int NIT = D_MODEL / 16;  // 48
    for (int it = 0; it < NIT; it++) {
        const int cur = it & 1;
        const bool more = (it + 1) < NIT;
        if (more) {
            const int ko = (it + 1) * 16;
            a0v = *(const float4*)(Ap + ko);
            a1v = *(const float4*)(Ap + ko + 4);
            w0v = *(const float4*)(Wp + ko);
            w1v = *(const float4*)(Wp + ko + 4);
        }

        // compute on buffer `cur`: two k=8 steps
#pragma unroll
        for (int ks = 0; ks < 2; ks++) {
            const int kq = ks * 8 + (lane & 3);
            // B fragments for all 4 n-tiles
            uint32_t bf[4][2];
#pragma unroll
            for (int nt = 0; nt < 4; nt++) {
                int n = wn * 32 + nt * 8 + (lane >> 2);
                bf[nt][0] = Ws[cur][kq][n];
                bf[nt][1] = Ws[cur][kq + 4][n];
            }
#pragma unroll
            for (int mt = 0; mt < 4; mt++) {
                int mr = wm * 64 + mt * 16 + (lane >> 2);
                uint32_t fa0 = As[cur][kq][mr];
                uint32_t fa1 = As[cur][kq][mr + 8];
                uint32_t fa2 = As[cur][kq + 4][mr];
                uint32_t fa3 = As[cur][kq + 4][mr + 8];
#pragma unroll
                for (int nt = 0; nt < 4; nt++)
                    mma_tf32(acc[mt][nt], fa0, fa1, fa2, fa3, bf[nt][0], bf[nt][1]);
            }
        }

        if (more) {
            const int nxt = cur ^ 1;
            float av[8] = {a0v.x,a0v.y,a0v.z,a0v.w,a1v.x,a1v.y,a1v.z,a1v.w};
            float wv[8] = {w0v.x,w0v.y,w0v.z,w0v.w,w1v.x,w1v.y,w1v.z,w1v.w};
            __syncthreads();   // mma reads of buffer `nxt` from prev iter done
#pragma unroll
            for (int j = 0; j < 8; j++) {
                As[nxt][sm_k0 + j][sm_m] = to_tf32(av[j]);
                Ws[nxt][sm_k0 + j][sm_m] = to_tf32(wv[j]);
            }
            __syncthreads();
        }
    }

    // ---- epilogue ----
#pragma unroll
    for (int mt = 0; mt < 4; mt++) {
#pragma unroll
        for (int nt = 0; nt < 4; nt++) {
            int r = row0 + wm * 64 + mt * 16 + (lane >> 2);
            int c = col0 + wn * 32 + nt * 8 + (lane & 3) * 2;
            float b0 = bias[c], b1 = bias[c + 1];
#pragma unroll
            for (int half = 0; half < 2; half++) {
                int rr = r + half * 8;
                float v0 = acc[mt][nt][half * 2 + 0] + b0;
                float v1 = acc[mt][nt][half * 2 + 1] + b1;
                size_t base;
                if (LAYOUT == 1) {
                    int b = rr >> 10, s = rr & 1023;
                    int h = c >> 6, d0 = c & 63;
                    base = (((size_t)(b * NUM_HEADS + h)) * SEQ + s) * HEAD_DIM + d0;
                } else {
                    base = (size_t)rr * D_MODEL + c;
                }
                *(float2*)(out + base) = make_float2(v0, v1);
            }
        }
    }
}

// ---------------- fused flash attention with spatial bias -------------------
// grid: (SEQ/128, BATCH*NUM_HEADS), 256 threads, ~134KB dynamic smem
__global__ __launch_bounds__(256) void attn_kernel(const float* __restrict__ sbias)
{
    extern __shared__ float sm[];
    float* Qs  = sm;                    // [64][128]  (d-major, transposed)
    float* KV  = sm + 64 * 128;         // K view [64][128] / V view [128][68]
    float* Ps  = KV + 8704;             // [128][132]
    float* qcx = Ps + 128 * 132;
    float* qcy = qcx + 128;
    float* kcx = qcy + 128;
    float* kcy = kcx + 128;

    const int t  = threadIdx.x;
    const int tx = t & 15, ty = t >> 4;
    const int bh = blockIdx.y;
    const int b  = bh / NUM_HEADS, h = bh % NUM_HEADS;
    const int q0 = blockIdx.x * 128;
    const float sb = sbias[h];
    const size_t headbase = (size_t)bh * SEQ * HEAD_DIM;

    // load Q tile transposed: Qs[d][r]
    {
        int r = t >> 1;
        int dbase = (t & 1) * 32;
        const float* qp = g_Q + headbase + (size_t)(q0 + r) * HEAD_DIM + dbase;
#pragma unroll
        for (int u = 0; u < 8; u++) {
            float4 v = *(const float4*)(qp + u * 4);
            int d = dbase + u * 4;
            Qs[(d+0)*128 + r] = v.x;
            Qs[(d+1)*128 + r] = v.y;
            Qs[(d+2)*128 + r] = v.z;
            Qs[(d+3)*128 + r] = v.w;
        }
    }
    if (t < 128) {
        qcx[t] = g_cx[b * SEQ + q0 + t];
        qcy[t] = g_cy[b * SEQ + q0 + t];
    }

    float m[8], l[8], acc[8][4];
#pragma unroll
    for (int i = 0; i < 8; i++) {
        m[i] = -CUDART_INF_F; l[i] = 0.f;
#pragma unroll
        for (int j = 0; j < 4; j++) acc[i][j] = 0.f;
    }
    float qx[8], qy[8];

    for (int kt = 0; kt < SEQ / 128; kt++) {
        const int k0 = kt * 128;
        // load K tile transposed into KV: K[d][c]
        {
            int r = t >> 1;
            int dbase = (t & 1) * 32;
            const float* kp = g_K + headbase + (size_t)(k0 + r) * HEAD_DIM + dbase;
#pragma unroll
            for (int u = 0; u < 8; u++) {
                float4 v = *(const float4*)(kp + u * 4);
                int d = dbase + u * 4;
                KV[(d+0)*128 + r] = v.x;
                KV[(d+1)*128 + r] = v.y;
                KV[(d+2)*128 + r] = v.z;
                KV[(d+3)*128 + r] = v.w;
            }
        }
        if (t < 128) {
            kcx[t] = g_cx[b * SEQ + k0 + t];
            kcy[t] = g_cy[b * SEQ + k0 + t];
        }
        __syncthreads();
        if (kt == 0) {
#pragma unroll
            for (int i = 0; i < 8; i++) { qx[i] = qcx[ty*8+i]; qy[i] = qcy[ty*8+i]; }
        }

        // ---- scores: S[r][c] = sum_d Q[r,d]*K[c,d]
        float sc[8][8];
#pragma unroll
        for (int i = 0; i < 8; i++)
#pragma unroll
            for (int j = 0; j < 8; j++) sc[i][j] = 0.f;

#pragma unroll 4
        for (int d = 0; d < 64; d++) {
            float4 a0 = *(const float4*)&Qs[d*128 + ty*8];
            float4 a1 = *(const float4*)&Qs[d*128 + ty*8 + 4];
            float4 b0 = *(const float4*)&KV[d*128 + tx*8];
            float4 b1 = *(const float4*)&KV[d*128 + tx*8 + 4];
            float ar[8] = {a0.x,a0.y,a0.z,a0.w,a1.x,a1.y,a1.z,a1.w};
            float br[8] = {b0.x,b0.y,b0.z,b0.w,b1.x,b1.y,b1.z,b1.w};
#pragma unroll
            for (int i = 0; i < 8; i++)
#pragma unroll
                for (int j = 0; j < 8; j++) sc[i][j] += ar[i] * br[j];
        }

        // ---- spatial bias + scale, move to exp2 domain
        float kx[8], ky[8];
#pragma unroll
        for (int j = 0; j < 8; j++) { kx[j] = kcx[tx*8+j]; ky[j] = kcy[tx*8+j]; }
#pragma unroll
        for (int i = 0; i < 8; i++)
#pragma unroll
            for (int j = 0; j < 8; j++) {
                float dx = qx[i] - kx[j], dy = qy[i] - ky[j];
                float dist = sqrtf(dx*dx + dy*dy);
                sc[i][j] = (sc[i][j] * 0.125f - dist * sb) * LOG2E;
            }

        // ---- online softmax (16 lanes share each row group)
#pragma unroll
        for (int i = 0; i < 8; i++) {
            float v = sc[i][0];
#pragma unroll
            for (int j = 1; j < 8; j++) v = fmaxf(v, sc[i][j]);
            v = fmaxf(v, __shfl_xor_sync(0xffffffffu, v, 1));
            v = fmaxf(v, __shfl_xor_sync(0xffffffffu, v, 2));
            v = fmaxf(v, __shfl_xor_sync(0xffffffffu, v, 4));
            v = fmaxf(v, __shfl_xor_sync(0xffffffffu, v, 8));
            float mnew = fmaxf(m[i], v);
            float scale = exp2f(m[i] - mnew);
            m[i] = mnew;
            float s = 0.f;
#pragma unroll
            for (int j = 0; j < 8; j++) {
                float p = exp2f(sc[i][j] - mnew);
                sc[i][j] = p;
                s += p;
            }
            s += __shfl_xor_sync(0xffffffffu, s, 1);
            s += __shfl_xor_sync(0xffffffffu, s, 2);
            s += __shfl_xor_sync(0xffffffffu, s, 4);
            s += __shfl_xor_sync(0xffffffffu, s, 8);
            l[i] = l[i] * scale + s;
#pragma unroll
            for (int jd = 0; jd < 4; jd++) acc[i][jd] *= scale;
        }

        // ---- stage P
#pragma unroll
        for (int i = 0; i < 8; i++) {
            int r = ty * 8 + i;
            *(float4*)&Ps[r*132 + tx*8]     = make_float4(sc[i][0], sc[i][1], sc[i][2], sc[i][3]);
            *(float4*)&Ps[r*132 + tx*8 + 4] = make_float4(sc[i][4], sc[i][5], sc[i][6], sc[i][7]);
        }
        __syncthreads();   // K reads done + P visible before V overwrites KV

        // ---- load V: V[c][d] padded to 68
        {
            int c = t >> 1;
            int dbase = (t & 1) * 32;
            const float* vp = g_V + headbase + (size_t)(k0 + c) * HEAD_DIM + dbase;
#pragma unroll
            for (int u = 0; u < 8; u++)
                *(float4*)&KV[c*68 + dbase + u*4] = *(const float4*)(vp + u*4);
        }
        __syncthreads();

        // ---- O += P @ V  (rows ty*8..+7, dims tx*4..+3)
#pragma unroll 1
        for (int cc = 0; cc < 32; cc++) {
            int c4 = cc * 4;
            float4 pv[8];
#pragma unroll
            for (int i = 0; i < 8; i++) pv[i] = *(const float4*)&Ps[(ty*8+i)*132 + c4];
            float4 vv[4];
#pragma unroll
            for (int u = 0; u < 4; u++) vv[u] = *(const float4*)&KV[(c4+u)*68 + tx*4];
#pragma unroll
            for (int i = 0; i < 8; i++) {
                acc[i][0] += pv[i].x*vv[0].x + pv[i].y*vv[1].x + pv[i].z*vv[2].x + pv[i].w*vv[3].x;
                acc[i][1] += pv[i].x*vv[0].y + pv[i].y*vv[1].y + pv[i].z*vv[2].y + pv[i].w*vv[3].y;
                acc[i][2] += pv[i].x*vv[0].z + pv[i].y*vv[1].z + pv[i].z*vv[2].z + pv[i].w*vv[3].z;
                acc[i][3] += pv[i].x*vv[0].w + pv[i].y*vv[1].w + pv[i].z*vv[2].w + pv[i].w*vv[3].w;
            }
        }
        __syncthreads();   // before next iter overwrites KV / kc
    }

    // ---- finalize: write [b, s, h*64+d] flat
#pragma unroll
    for (int i = 0; i < 8; i++) {
        int r = q0 + ty * 8 + i;
        float inv = 1.f / l[i];
        size_t base = ((size_t)(b * SEQ + r)) * D_MODEL + h * HEAD_DIM + tx * 4;
        *(float4*)(g_att + base) = make_float4(acc[i][0]*inv, acc[i][1]*inv,
                                               acc[i][2]*inv, acc[i][3]*inv);
    }
}

// ---------------- launch ----------------------------------------------------
extern "C" void kernel_launch(void* const* d_in, const int* in_sizes, int n_in,
                              void* d_out, int out_size)
{
    const float* x     = (const float*)d_in[0];
    const float* boxes = (const float*)d_in[1];
    const float* Wq    = (const float*)d_in[2];
    const float* bq    = (const float*)d_in[3];
    const float* Wk    = (const float*)d_in[4];
    const float* bk    = (const float*)d_in[5];
    const float* Wv    = (const float*)d_in[6];
    const float* bv    = (const float*)d_in[7];
    const float* Wo    = (const float*)d_in[8];
    const float* bo    = (const float*)d_in[9];
    const float* sbias = (const float*)d_in[10];
    float* out = (float*)d_out;

    float *pQ, *pK, *pV, *pAtt;
    cudaGetSymbolAddress((void**)&pQ,   g_Q);
    cudaGetSymbolAddress((void**)&pK,   g_K);
    cudaGetSymbolAddress((void**)&pV,   g_V);
    cudaGetSymbolAddress((void**)&pAtt, g_att);

    const int ATTN_SMEM = (64*128 + 8704 + 128*132 + 4*128) * 4;  // 137216 B
    cudaFuncSetAttribute(attn_kernel, cudaFuncAttributeMaxDynamicSharedMemorySize, ATTN_SMEM);

    centers_kernel<<<(NTOK + 255) / 256, 256>>>(boxes);

    dim3 ggrid(D_MODEL / 128, NTOK / 128);   // (6, 32)
    gemm_tc_kernel<1><<<ggrid, 256>>>(x, Wq, bq, pQ);
    gemm_tc_kernel<1><<<ggrid, 256>>>(x, Wk, bk, pK);
    gemm_tc_kernel<1><<<ggrid, 256>>>(x, Wv, bv, pV);

    dim3 agrid(SEQ / 128, BATCH * NUM_HEADS); // (8, 48)
    attn_kernel<<<agrid, 256, ATTN_SMEM>>>(sbias);

    gemm_tc_kernel<0><<<ggrid, 256>>>(pAtt, Wo, bo, out);
}

// round 5
// speedup vs baseline: 2.3029x; 1.6944x over previous
#include <cuda_runtime.h>
#include <math_constants.h>
#include <math.h>
#include <stdint.h>

#define D_MODEL   768
#define NUM_HEADS 12
#define HEAD_DIM  64
#define BATCH     4
#define SEQ       1024
#define NTOK      (BATCH*SEQ)
#define LOG2E     1.4426950408889634f

// ---------------- scratch ----------------------------------------------------
__device__ float g_Q[NTOK * D_MODEL];     // [b,h,s,d]
__device__ float g_K[NTOK * D_MODEL];     // [b,h,s,d]
__device__ float g_V[NTOK * D_MODEL];     // [b,h,s,d]
__device__ float g_att[NTOK * D_MODEL];   // [b,s, h*64+d] flat [4096,768]
__device__ float g_cx[NTOK];
__device__ float g_cy[NTOK];

// ---------------- box centers ----------------------------------------------
__global__ void centers_kernel(const float* __restrict__ boxes) {
    int i = blockIdx.x * blockDim.x + threadIdx.x;
    if (i < NTOK) {
        float4 bx = *(const float4*)(boxes + (size_t)i * 4);
        g_cx[i] = (bx.x + bx.z) * 0.5f;
        g_cy[i] = (bx.y + bx.w) * 0.5f;
    }
}

// ---------------- tf32 helpers ----------------------------------------------
__device__ __forceinline__ uint32_t to_tf32(float x) {
    uint32_t r;
    asm("cvt.rna.tf32.f32 %0, %1;" : "=r"(r) : "f"(x));
    return r;
}

__device__ __forceinline__ void mma_tf32(float* c, uint32_t a0, uint32_t a1,
                                         uint32_t a2, uint32_t a3,
                                         uint32_t b0, uint32_t b1) {
    asm volatile(
        "mma.sync.aligned.m16n8k8.row.col.f32.tf32.tf32.f32 "
        "{%0,%1,%2,%3}, {%4,%5,%6,%7}, {%8,%9}, {%0,%1,%2,%3};\n"
        : "+f"(c[0]), "+f"(c[1]), "+f"(c[2]), "+f"(c[3])
        : "r"(a0), "r"(a1), "r"(a2), "r"(a3), "r"(b0), "r"(b1));
}

// ---------------- TF32 tensor-core GEMM ------------------------------------
// BM=BN=128, BK=16. Paired-k smem layout: row stride 24 words, slot
// g*8+2q+{0,1} = {X[m][g*8+q], X[m][g*8+q+4]} -> every fragment pair is one
// LDS.64, conflict-free (24m+2q distinct mod 32 per 16-lane phase).
// Double buffered, ONE __syncthreads per iteration, 2 CTAs/SM.
#define GSTRIDE 24
#define GEMM_SMEM_BYTES (2 * 2 * 128 * GSTRIDE * 4)   // A+W, 2 bufs: 49152 B

template<int LAYOUT>
__global__ __launch_bounds__(256, 2) void gemm_tc_kernel(
    const float* __restrict__ A, const float* __restrict__ W,
    const float* __restrict__ bias, float* __restrict__ out)
{
    extern __shared__ uint32_t gsm[];
    uint32_t* As = gsm;                     // [2][128][24]
    uint32_t* Ws = gsm + 2 * 128 * GSTRIDE;

    const int t    = threadIdx.x;
    const int lane = t & 31;
    const int warp = t >> 5;
    const int wm   = warp & 1;
    const int wn   = warp >> 1;
    const int row0 = blockIdx.y * 128;
    const int col0 = blockIdx.x * 128;

    const int sm_m  = t >> 1;
    const int sm_k0 = (t & 1) * 8;
    const float* Ap = A + (size_t)(row0 + sm_m) * D_MODEL + sm_k0;
    const float* Wp = W + (size_t)(col0 + sm_m) * D_MODEL + sm_k0;

    float acc[4][4][4];
#pragma unroll
    for (int mt = 0; mt < 4; mt++)
#pragma unroll
        for (int nt = 0; nt < 4; nt++)
#pragma unroll
            for (int r = 0; r < 4; r++) acc[mt][nt][r] = 0.f;

    float4 a0v, a1v, w0v, w1v;

    // stage tile 0
    a0v = *(const float4*)(Ap);     a1v = *(const float4*)(Ap + 4);
    w0v = *(const float4*)(Wp);     w1v = *(const float4*)(Wp + 4);
    {
        uint32_t* ar = &As[sm_m * GSTRIDE + sm_k0];
        uint32_t* wr = &Ws[sm_m * GSTRIDE + sm_k0];
        *(uint2*)(ar + 0) = make_uint2(to_tf32(a0v.x), to_tf32(a1v.x));
        *(uint2*)(ar + 2) = make_uint2(to_tf32(a0v.y), to_tf32(a1v.y));
        *(uint2*)(ar + 4) = make_uint2(to_tf32(a0v.z), to_tf32(a1v.z));
        *(uint2*)(ar + 6) = make_uint2(to_tf32(a0v.w), to_tf32(a1v.w));
        *(uint2*)(wr + 0) = make_uint2(to_tf32(w0v.x), to_tf32(w1v.x));
        *(uint2*)(wr + 2) = make_uint2(to_tf32(w0v.y), to_tf32(w1v.y));
        *(uint2*)(wr + 4) = make_uint2(to_tf32(w0v.z), to_tf32(w1v.z));
        *(uint2*)(wr + 6) = make_uint2(to_tf32(w0v.w), to_tf32(w1v.w));
    }
    __syncthreads();

    const int NIT = D_MODEL / 16;  // 48
    for (int it = 0; it < NIT; it++) {
        const int cur  = it & 1;
        const bool more = (it + 1) < NIT;
        if (more) {
            const int ko = (it + 1) * 16;
            a0v = *(const float4*)(Ap + ko);  a1v = *(const float4*)(Ap + ko + 4);
            w0v = *(const float4*)(Wp + ko);  w1v = *(const float4*)(Wp + ko + 4);
        }

        const uint32_t* Ab = &As[cur * 128 * GSTRIDE];
        const uint32_t* Wb = &Ws[cur * 128 * GSTRIDE];
#pragma unroll
        for (int ks = 0; ks < 2; ks++) {
            const int base = ks * 8 + 2 * (lane & 3);
            uint2 bf[4];
#pragma unroll
            for (int nt = 0; nt < 4; nt++) {
                int n = wn * 32 + nt * 8 + (lane >> 2);
                bf[nt] = *(const uint2*)&Wb[n * GSTRIDE + base];
            }
#pragma unroll
            for (int mt = 0; mt < 4; mt++) {
                int mr = wm * 64 + mt * 16 + (lane >> 2);
                uint2 lo = *(const uint2*)&Ab[mr * GSTRIDE + base];
                uint2 hi = *(const uint2*)&Ab[(mr + 8) * GSTRIDE + base];
#pragma unroll
                for (int nt = 0; nt < 4; nt++)
                    mma_tf32(acc[mt][nt], lo.x, hi.x, lo.y, hi.y, bf[nt].x, bf[nt].y);
            }
        }

        if (more) {
            const int nxt = cur ^ 1;
            uint32_t* ar = &As[(nxt * 128 + sm_m) * GSTRIDE + sm_k0];
            uint32_t* wr = &Ws[(nxt * 128 + sm_m) * GSTRIDE + sm_k0];
            *(uint2*)(ar + 0) = make_uint2(to_tf32(a0v.x), to_tf32(a1v.x));
            *(uint2*)(ar + 2) = make_uint2(to_tf32(a0v.y), to_tf32(a1v.y));
            *(uint2*)(ar + 4) = make_uint2(to_tf32(a0v.z), to_tf32(a1v.z));
            *(uint2*)(ar + 6) = make_uint2(to_tf32(a0v.w), to_tf32(a1v.w));
            *(uint2*)(wr + 0) = make_uint2(to_tf32(w0v.x), to_tf32(w1v.x));
            *(uint2*)(wr + 2) = make_uint2(to_tf32(w0v.y), to_tf32(w1v.y));
            *(uint2*)(wr + 4) = make_uint2(to_tf32(w0v.z), to_tf32(w1v.z));
            *(uint2*)(wr + 6) = make_uint2(to_tf32(w0v.w), to_tf32(w1v.w));
        }
        __syncthreads();
    }

    // ---- epilogue ----
#pragma unroll
    for (int mt = 0; mt < 4; mt++) {
#pragma unroll
        for (int nt = 0; nt < 4; nt++) {
            int r = row0 + wm * 64 + mt * 16 + (lane >> 2);
            int c = col0 + wn * 32 + nt * 8 + (lane & 3) * 2;
            float b0 = bias[c], b1 = bias[c + 1];
#pragma unroll
            for (int half = 0; half < 2; half++) {
                int rr = r + half * 8;
                float v0 = acc[mt][nt][half * 2 + 0] + b0;
                float v1 = acc[mt][nt][half * 2 + 1] + b1;
                size_t base;
                if (LAYOUT == 1) {
                    int b = rr >> 10, s = rr & 1023;
                    int h = c >> 6, d0 = c & 63;
                    base = (((size_t)(b * NUM_HEADS + h)) * SEQ + s) * HEAD_DIM + d0;
                } else {
                    base = (size_t)rr * D_MODEL + c;
                }
                *(float2*)(out + base) = make_float2(v0, v1);
            }
        }
    }
}

// ---------------- tensor-core flash attention with spatial bias -------------
// 8 warps x 16 rows each. TF32 mma for S=QK^T and O+=PV. Softmax warp-local
// (quad shfl). Q/K paired layout stride 72; V natural stride 72; P via smem
// stride 132. grid (SEQ/128, B*H), 256 threads, ~180KB dynamic smem.
#define AQ_STR 72
#define AK_STR 72
#define AV_STR 72
#define AP_STR 132
#define OFF_Q   0
#define OFF_K   (128*AQ_STR)
#define OFF_V   (OFF_K + 128*AK_STR)
#define OFF_P   (OFF_V + 128*AV_STR)
#define OFF_QCX (OFF_P + 128*AP_STR)
#define OFF_QCY (OFF_QCX + 128)
#define OFF_KCX (OFF_QCY + 128)
#define OFF_KCY (OFF_KCX + 128)
#define ATTN_SMEM_BYTES ((OFF_KCY + 128) * 4)

// stage one [128 x 64] fp32 tile into PAIRED tf32 layout (stride 72)
__device__ __forceinline__ void stage_paired(uint32_t* dst, const float* src,
                                             int t) {
    const int tr = t >> 1;
    const int half = t & 1;
    const float* p = src + (size_t)tr * HEAD_DIM + half * 32;
    float4 f[8];
#pragma unroll
    for (int u = 0; u < 8; u++) f[u] = *(const float4*)(p + 4 * u);
    uint32_t* row = dst + tr * AQ_STR + half * 32;
#pragma unroll
    for (int gg = 0; gg < 4; gg++) {
        float4 lo = f[2 * gg], hi = f[2 * gg + 1];
        *(uint2*)(row + gg * 8 + 0) = make_uint2(to_tf32(lo.x), to_tf32(hi.x));
        *(uint2*)(row + gg * 8 + 2) = make_uint2(to_tf32(lo.y), to_tf32(hi.y));
        *(uint2*)(row + gg * 8 + 4) = make_uint2(to_tf32(lo.z), to_tf32(hi.z));
        *(uint2*)(row + gg * 8 + 6) = make_uint2(to_tf32(lo.w), to_tf32(hi.w));
    }
}

__global__ __launch_bounds__(256) void attn_kernel(const float* __restrict__ sbias)
{
    extern __shared__ uint32_t smu[];
    uint32_t* Qs = smu + OFF_Q;
    uint32_t* Ks = smu + OFF_K;
    uint32_t* Vs = smu + OFF_V;
    uint32_t* Ps = smu + OFF_P;
    float* qcx = (float*)(smu + OFF_QCX);
    float* qcy = (float*)(smu + OFF_QCY);
    float* kcx = (float*)(smu + OFF_KCX);
    float* kcy = (float*)(smu + OFF_KCY);

    const int t    = threadIdx.x;
    const int lane = t & 31;
    const int warp = t >> 5;
    const int bh = blockIdx.y;
    const int b  = bh / NUM_HEADS, h = bh % NUM_HEADS;
    const int q0 = blockIdx.x * 128;
    const float sb2 = sbias[h] * LOG2E;
    const float sc2 = 0.125f * LOG2E;
    const size_t headbase = (size_t)bh * SEQ * HEAD_DIM;

    const int r0 = warp * 16 + (lane >> 2);   // row 0 of this thread
    const int r1 = r0 + 8;

    // ---- stage Q + q centers ----
    stage_paired(Qs, g_Q + headbase + (size_t)q0 * HEAD_DIM, t);
    if (t < 128) {
        qcx[t] = g_cx[b * SEQ + q0 + t];
        qcy[t] = g_cy[b * SEQ + q0 + t];
    }
    __syncthreads();

    // Q fragments resident: qf[ks] = {a0,a1,a2,a3}
    uint4 qf[8];
#pragma unroll
    for (int ks = 0; ks < 8; ks++) {
        uint2 lo = *(const uint2*)&Qs[r0 * AQ_STR + ks * 8 + 2 * (lane & 3)];
        uint2 hi = *(const uint2*)&Qs[r1 * AQ_STR + ks * 8 + 2 * (lane & 3)];
        qf[ks] = make_uint4(lo.x, hi.x, lo.y, hi.y);
    }
    const float qx0 = qcx[r0], qy0 = qcy[r0];
    const float qx1 = qcx[r1], qy1 = qcy[r1];

    float m0 = -CUDART_INF_F, m1 = -CUDART_INF_F, l0 = 0.f, l1 = 0.f;
    float oacc[8][4];
#pragma unroll
    for (int nt = 0; nt < 8; nt++)
#pragma unroll
        for (int r = 0; r < 4; r++) oacc[nt][r] = 0.f;

    for (int kt = 0; kt < SEQ / 128; kt++) {
        const int k0 = kt * 128;
        __syncthreads();   // previous Ks/Vs reads complete
        // ---- stage K (paired), V (natural tf32), k centers ----
        stage_paired(Ks, g_K + headbase + (size_t)k0 * HEAD_DIM, t);
        {
            const int tr = t >> 1;
            const int cb = (t & 1) * 32;
            const float* vp = g_V + headbase + (size_t)(k0 + tr) * HEAD_DIM + cb;
            uint32_t* row = Vs + tr * AV_STR + cb;
#pragma unroll
            for (int u = 0; u < 8; u++) {
                float4 v = *(const float4*)(vp + 4 * u);
                *(uint4*)(row + 4 * u) =
                    make_uint4(to_tf32(v.x), to_tf32(v.y), to_tf32(v.z), to_tf32(v.w));
            }
        }
        if (t < 128) {
            kcx[t] = g_cx[b * SEQ + k0 + t];
            kcy[t] = g_cy[b * SEQ + k0 + t];
        }
        __syncthreads();

        // ---- S = Q @ K^T (16 n-tiles of 8 cols) ----
        float sacc[16][4];
#pragma unroll
        for (int nt = 0; nt < 16; nt++) {
            sacc[nt][0] = sacc[nt][1] = sacc[nt][2] = sacc[nt][3] = 0.f;
            const uint32_t* kr = &Ks[(nt * 8 + (lane >> 2)) * AK_STR + 2 * (lane & 3)];
#pragma unroll
            for (int ks = 0; ks < 8; ks++) {
                uint2 bv = *(const uint2*)(kr + ks * 8);
                mma_tf32(sacc[nt], qf[ks].x, qf[ks].y, qf[ks].z, qf[ks].w, bv.x, bv.y);
            }
        }

        // ---- bias + scale (exp2 domain), track row maxima ----
        float pm0 = -CUDART_INF_F, pm1 = -CUDART_INF_F;
#pragma unroll
        for (int nt = 0; nt < 16; nt++) {
            const int c0 = nt * 8 + 2 * (lane & 3);
            const float kx0 = kcx[c0], kx1 = kcx[c0 + 1];
            const float ky0 = kcy[c0], ky1 = kcy[c0 + 1];
            float dx, dy;
            dx = qx0 - kx0; dy = qy0 - ky0;
            sacc[nt][0] = sacc[nt][0] * sc2 - sqrtf(dx * dx + dy * dy) * sb2;
            dx = qx0 - kx1; dy = qy0 - ky1;
            sacc[nt][1] = sacc[nt][1] * sc2 - sqrtf(dx * dx + dy * dy) * sb2;
            dx = qx1 - kx0; dy = qy1 - ky0;
            sacc[nt][2] = sacc[nt][2] * sc2 - sqrtf(dx * dx + dy * dy) * sb2;
            dx = qx1 - kx1; dy = qy1 - ky1;
            sacc[nt][3] = sacc[nt][3] * sc2 - sqrtf(dx * dx + dy * dy) * sb2;
            pm0 = fmaxf(pm0, fmaxf(sacc[nt][0], sacc[nt][1]));
            pm1 = fmaxf(pm1, fmaxf(sacc[nt][2], sacc[nt][3]));
        }
        // quad reduction (lanes of a quad share rows)
        pm0 = fmaxf(pm0, __shfl_xor_sync(0xffffffffu, pm0, 1));
        pm0 = fmaxf(pm0, __shfl_xor_sync(0xffffffffu, pm0, 2));
        pm1 = fmaxf(pm1, __shfl_xor_sync(0xffffffffu, pm1, 1));
        pm1 = fmaxf(pm1, __shfl_xor_sync(0xffffffffu, pm1, 2));

        const float mn0 = fmaxf(m0, pm0), mn1 = fmaxf(m1, pm1);
        const float sc0 = exp2f(m0 - mn0), sc1 = exp2f(m1 - mn1);
        m0 = mn0; m1 = mn1;
#pragma unroll
        for (int nt = 0; nt < 8; nt++) {
            oacc[nt][0] *= sc0; oacc[nt][1] *= sc0;
            oacc[nt][2] *= sc1; oacc[nt][3] *= sc1;
        }

        // ---- p = exp2, row sums, store P (tf32) ----
        float s0 = 0.f, s1 = 0.f;
#pragma unroll
        for (int nt = 0; nt < 16; nt++) {
            const int c0 = nt * 8 + 2 * (lane & 3);
            float p00 = exp2f(sacc[nt][0] - mn0);
            float p01 = exp2f(sacc[nt][1] - mn0);
            float p10 = exp2f(sacc[nt][2] - mn1);
            float p11 = exp2f(sacc[nt][3] - mn1);
            s0 += p00 + p01; s1 += p10 + p11;
            *(uint2*)&Ps[r0 * AP_STR + c0] = make_uint2(to_tf32(p00), to_tf32(p01));
            *(uint2*)&Ps[r1 * AP_STR + c0] = make_uint2(to_tf32(p10), to_tf32(p11));
        }
        s0 += __shfl_xor_sync(0xffffffffu, s0, 1);
        s0 += __shfl_xor_sync(0xffffffffu, s0, 2);
        s1 += __shfl_xor_sync(0xffffffffu, s1, 1);
        s1 += __shfl_xor_sync(0xffffffffu, s1, 2);
        l0 = l0 * sc0 + s0;
        l1 = l1 * sc1 + s1;

        __syncwarp();  // P region is warp-private: warp wrote rows it now reads

        // ---- O += P @ V ----
#pragma unroll
        for (int ks = 0; ks < 16; ks++) {
            const int k = ks * 8 + (lane & 3);
            uint32_t pa0 = Ps[r0 * AP_STR + k];
            uint32_t pa1 = Ps[r1 * AP_STR + k];
            uint32_t pa2 = Ps[r0 * AP_STR + k + 4];
            uint32_t pa3 = Ps[r1 * AP_STR + k + 4];
            const uint32_t* vr0 = &Vs[k * AV_STR + (lane >> 2)];
            const uint32_t* vr1 = &Vs[(k + 4) * AV_STR + (lane >> 2)];
#pragma unroll
            for (int nt = 0; nt < 8; nt++) {
                uint32_t vb0 = vr0[nt * 8];
                uint32_t vb1 = vr1[nt * 8];
                mma_tf32(oacc[nt], pa0, pa1, pa2, pa3, vb0, vb1);
            }
        }
    }

    // ---- finalize ----
    const float inv0 = 1.f / l0, inv1 = 1.f / l1;
#pragma unroll
    for (int nt = 0; nt < 8; nt++) {
        const int d0 = nt * 8 + 2 * (lane & 3);
        size_t base0 = ((size_t)(b * SEQ + q0 + r0)) * D_MODEL + h * HEAD_DIM + d0;
        size_t base1 = ((size_t)(b * SEQ + q0 + r1)) * D_MODEL + h * HEAD_DIM + d0;
        *(float2*)(g_att + base0) = make_float2(oacc[nt][0] * inv0, oacc[nt][1] * inv0);
        *(float2*)(g_att + base1) = make_float2(oacc[nt][2] * inv1, oacc[nt][3] * inv1);
    }
}

// ---------------- launch ----------------------------------------------------
extern "C" void kernel_launch(void* const* d_in, const int* in_sizes, int n_in,
                              void* d_out, int out_size)
{
    const float* x     = (const float*)d_in[0];
    const float* boxes = (const float*)d_in[1];
    const float* Wq    = (const float*)d_in[2];
    const float* bq    = (const float*)d_in[3];
    const float* Wk    = (const float*)d_in[4];
    const float* bk    = (const float*)d_in[5];
    const float* Wv    = (const float*)d_in[6];
    const float* bv    = (const float*)d_in[7];
    const float* Wo    = (const float*)d_in[8];
    const float* bo    = (const float*)d_in[9];
    const float* sbias = (const float*)d_in[10];
    float* out = (float*)d_out;

    float *pQ, *pK, *pV, *pAtt;
    cudaGetSymbolAddress((void**)&pQ,   g_Q);
    cudaGetSymbolAddress((void**)&pK,   g_K);
    cudaGetSymbolAddress((void**)&pV,   g_V);
    cudaGetSymbolAddress((void**)&pAtt, g_att);

    cudaFuncSetAttribute(gemm_tc_kernel<0>,
        cudaFuncAttributeMaxDynamicSharedMemorySize, GEMM_SMEM_BYTES);
    cudaFuncSetAttribute(gemm_tc_kernel<1>,
        cudaFuncAttributeMaxDynamicSharedMemorySize, GEMM_SMEM_BYTES);
    cudaFuncSetAttribute(attn_kernel,
        cudaFuncAttributeMaxDynamicSharedMemorySize, ATTN_SMEM_BYTES);

    centers_kernel<<<(NTOK + 255) / 256, 256>>>(boxes);

    dim3 ggrid(D_MODEL / 128, NTOK / 128);   // (6, 32)
    gemm_tc_kernel<1><<<ggrid, 256, GEMM_SMEM_BYTES>>>(x, Wq, bq, pQ);
    gemm_tc_kernel<1><<<ggrid, 256, GEMM_SMEM_BYTES>>>(x, Wk, bk, pK);
    gemm_tc_kernel<1><<<ggrid, 256, GEMM_SMEM_BYTES>>>(x, Wv, bv, pV);

    dim3 agrid(SEQ / 128, BATCH * NUM_HEADS); // (8, 48)
    attn_kernel<<<agrid, 256, ATTN_SMEM_BYTES>>>(sbias);

    gemm_tc_kernel<0><<<ggrid, 256, GEMM_SMEM_BYTES>>>(pAtt, Wo, bo, out);
}

// round 8
// speedup vs baseline: 2.7604x; 1.1987x over previous
#include <cuda_runtime.h>
#include <math_constants.h>
#include <math.h>
#include <stdint.h>

#define D_MODEL   768
#define NUM_HEADS 12
#define HEAD_DIM  64
#define BATCH     4
#define SEQ       1024
#define NTOK      (BATCH*SEQ)
#define LOG2E     1.4426950408889634f

// ---------------- scratch ----------------------------------------------------
__device__ float g_Q[NTOK * D_MODEL];     // [b,h,s,d]
__device__ float g_K[NTOK * D_MODEL];     // [b,h,s,d]
__device__ float g_V[NTOK * D_MODEL];     // [b,h,s,d]
__device__ float g_att[NTOK * D_MODEL];   // [b,s, h*64+d] flat [4096,768]
__device__ float g_cx[NTOK];
__device__ float g_cy[NTOK];

// ---------------- box centers ----------------------------------------------
__global__ void centers_kernel(const float* __restrict__ boxes) {
    int i = blockIdx.x * blockDim.x + threadIdx.x;
    if (i < NTOK) {
        float4 bx = *(const float4*)(boxes + (size_t)i * 4);
        g_cx[i] = (bx.x + bx.z) * 0.5f;
        g_cy[i] = (bx.y + bx.w) * 0.5f;
    }
}

// ---------------- tf32 helpers ----------------------------------------------
__device__ __forceinline__ uint32_t to_tf32(float x) {
    uint32_t r;
    asm("cvt.rna.tf32.f32 %0, %1;" : "=r"(r) : "f"(x));
    return r;
}

__device__ __forceinline__ void mma_tf32(float* c, uint32_t a0, uint32_t a1,
                                         uint32_t a2, uint32_t a3,
                                         uint32_t b0, uint32_t b1) {
    asm volatile(
        "mma.sync.aligned.m16n8k8.row.col.f32.tf32.tf32.f32 "
        "{%0,%1,%2,%3}, {%4,%5,%6,%7}, {%8,%9}, {%0,%1,%2,%3};\n"
        : "+f"(c[0]), "+f"(c[1]), "+f"(c[2]), "+f"(c[3])
        : "r"(a0), "r"(a1), "r"(a2), "r"(a3), "r"(b0), "r"(b1));
}

// ---------------- TF32 tensor-core GEMM body --------------------------------
// BM=BN=128, BK=16, paired-k smem (stride 24), double buffered, one barrier
// per iteration. LAYOUT 1: scatter [b,h,s,d]; LAYOUT 0: flat [n, D_MODEL].
#define GSTRIDE 24
#define GEMM_SMEM_BYTES (2 * 2 * 128 * GSTRIDE * 4)   // 49152 B

template<int LAYOUT>
__device__ __forceinline__ void gemm_body(
    const float* __restrict__ A, const float* __restrict__ W,
    const float* __restrict__ bias, float* __restrict__ out)
{
    extern __shared__ uint32_t gsm[];
    uint32_t* As = gsm;                     // [2][128][24]
    uint32_t* Ws = gsm + 2 * 128 * GSTRIDE;

    const int t    = threadIdx.x;
    const int lane = t & 31;
    const int warp = t >> 5;
    const int wm   = warp & 1;
    const int wn   = warp >> 1;
    const int row0 = blockIdx.y * 128;
    const int col0 = blockIdx.x * 128;

    const int sm_m  = t >> 1;
    const int sm_k0 = (t & 1) * 8;
    const float* Ap = A + (size_t)(row0 + sm_m) * D_MODEL + sm_k0;
    const float* Wp = W + (size_t)(col0 + sm_m) * D_MODEL + sm_k0;

    float acc[4][4][4];
#pragma unroll
    for (int mt = 0; mt < 4; mt++)
#pragma unroll
        for (int nt = 0; nt < 4; nt++)
#pragma unroll
            for (int r = 0; r < 4; r++) acc[mt][nt][r] = 0.f;

    float4 a0v, a1v, w0v, w1v;
    a0v = *(const float4*)(Ap);     a1v = *(const float4*)(Ap + 4);
    w0v = *(const float4*)(Wp);     w1v = *(const float4*)(Wp + 4);
    {
        uint32_t* ar = &As[sm_m * GSTRIDE + sm_k0];
        uint32_t* wr = &Ws[sm_m * GSTRIDE + sm_k0];
        *(uint2*)(ar + 0) = make_uint2(to_tf32(a0v.x), to_tf32(a1v.x));
        *(uint2*)(ar + 2) = make_uint2(to_tf32(a0v.y), to_tf32(a1v.y));
        *(uint2*)(ar + 4) = make_uint2(to_tf32(a0v.z), to_tf32(a1v.z));
        *(uint2*)(ar + 6) = make_uint2(to_tf32(a0v.w), to_tf32(a1v.w));
        *(uint2*)(wr + 0) = make_uint2(to_tf32(w0v.x), to_tf32(w1v.x));
        *(uint2*)(wr + 2) = make_uint2(to_tf32(w0v.y), to_tf32(w1v.y));
        *(uint2*)(wr + 4) = make_uint2(to_tf32(w0v.z), to_tf32(w1v.z));
        *(uint2*)(wr + 6) = make_uint2(to_tf32(w0v.w), to_tf32(w1v.w));
    }
    __syncthreads();

    const int NIT = D_MODEL / 16;  // 48
    for (int it = 0; it < NIT; it++) {
        const int cur  = it & 1;
        const bool more = (it + 1) < NIT;
        if (more) {
            const int ko = (it + 1) * 16;
            a0v = *(const float4*)(Ap + ko);  a1v = *(const float4*)(Ap + ko + 4);
            w0v = *(const float4*)(Wp + ko);  w1v = *(const float4*)(Wp + ko + 4);
        }

        const uint32_t* Ab = &As[cur * 128 * GSTRIDE];
        const uint32_t* Wb = &Ws[cur * 128 * GSTRIDE];
#pragma unroll
        for (int ks = 0; ks < 2; ks++) {
            const int base = ks * 8 + 2 * (lane & 3);
            uint2 bf[4];
#pragma unroll
            for (int nt = 0; nt < 4; nt++) {
                int n = wn * 32 + nt * 8 + (lane >> 2);
                bf[nt] = *(const uint2*)&Wb[n * GSTRIDE + base];
            }
#pragma unroll
            for (int mt = 0; mt < 4; mt++) {
                int mr = wm * 64 + mt * 16 + (lane >> 2);
                uint2 lo = *(const uint2*)&Ab[mr * GSTRIDE + base];
                uint2 hi = *(const uint2*)&Ab[(mr + 8) * GSTRIDE + base];
#pragma unroll
                for (int nt = 0; nt < 4; nt++)
                    mma_tf32(acc[mt][nt], lo.x, hi.x, lo.y, hi.y, bf[nt].x, bf[nt].y);
            }
        }

        if (more) {
            const int nxt = cur ^ 1;
            uint32_t* ar = &As[(nxt * 128 + sm_m) * GSTRIDE + sm_k0];
            uint32_t* wr = &Ws[(nxt * 128 + sm_m) * GSTRIDE + sm_k0];
            *(uint2*)(ar + 0) = make_uint2(to_tf32(a0v.x), to_tf32(a1v.x));
            *(uint2*)(ar + 2) = make_uint2(to_tf32(a0v.y), to_tf32(a1v.y));
            *(uint2*)(ar + 4) = make_uint2(to_tf32(a0v.z), to_tf32(a1v.z));
            *(uint2*)(ar + 6) = make_uint2(to_tf32(a0v.w), to_tf32(a1v.w));
            *(uint2*)(wr + 0) = make_uint2(to_tf32(w0v.x), to_tf32(w1v.x));
            *(uint2*)(wr + 2) = make_uint2(to_tf32(w0v.y), to_tf32(w1v.y));
            *(uint2*)(wr + 4) = make_uint2(to_tf32(w0v.z), to_tf32(w1v.z));
            *(uint2*)(wr + 6) = make_uint2(to_tf32(w0v.w), to_tf32(w1v.w));
        }
        __syncthreads();
    }

#pragma unroll
    for (int mt = 0; mt < 4; mt++) {
#pragma unroll
        for (int nt = 0; nt < 4; nt++) {
            int r = row0 + wm * 64 + mt * 16 + (lane >> 2);
            int c = col0 + wn * 32 + nt * 8 + (lane & 3) * 2;
            float b0 = bias[c], b1 = bias[c + 1];
#pragma unroll
            for (int half = 0; half < 2; half++) {
                int rr = r + half * 8;
                float v0 = acc[mt][nt][half * 2 + 0] + b0;
                float v1 = acc[mt][nt][half * 2 + 1] + b1;
                size_t base;
                if (LAYOUT == 1) {
                    int b = rr >> 10, s = rr & 1023;
                    int h = c >> 6, d0 = c & 63;
                    base = (((size_t)(b * NUM_HEADS + h)) * SEQ + s) * HEAD_DIM + d0;
                } else {
                    base = (size_t)rr * D_MODEL + c;
                }
                *(float2*)(out + base) = make_float2(v0, v1);
            }
        }
    }
}

// fused QKV: blockIdx.z selects projection; x tile reused via L2
__global__ __launch_bounds__(256, 2) void gemm_qkv_kernel(
    const float* __restrict__ x,
    const float* __restrict__ Wq, const float* __restrict__ Wk,
    const float* __restrict__ Wv,
    const float* __restrict__ bq, const float* __restrict__ bk,
    const float* __restrict__ bv,
    float* __restrict__ oq, float* __restrict__ ok, float* __restrict__ ov)
{
    const int z = blockIdx.z;
    const float* W = (z == 0) ? Wq : (z == 1) ? Wk : Wv;
    const float* b = (z == 0) ? bq : (z == 1) ? bk : bv;
    float*       o = (z == 0) ? oq : (z == 1) ? ok : ov;
    gemm_body<1>(x, W, b, o);
}

__global__ __launch_bounds__(256, 2) void gemm_out_kernel(
    const float* __restrict__ A, const float* __restrict__ W,
    const float* __restrict__ bias, float* __restrict__ out)
{
    gemm_body<0>(A, W, bias, out);
}

// ---------------- tensor-core flash attention (no P smem) -------------------
// 8 warps x 16 rows. Per K-tile: two 64-col chunks; S frags -> softmax ->
// shuffle-transpose (c-frag -> a-frag) -> PV mma, all in registers.
// Smem: Q/K paired (stride 72), V natural (stride 72), centers. 110 KB ->
// 2 CTAs/SM.
#define AQ_STR 72
#define AV_STR 72
#define OFF_Q   0
#define OFF_K   (128*AQ_STR)
#define OFF_V   (2*128*AQ_STR)
#define OFF_QCX (3*128*AQ_STR)
#define OFF_QCY (OFF_QCX + 128)
#define OFF_KCX (OFF_QCY + 128)
#define OFF_KCY (OFF_KCX + 128)
#define ATTN_SMEM_BYTES ((OFF_KCY + 128) * 4)   // 112640 B

__device__ __forceinline__ void stage_paired(uint32_t* dst, const float* src,
                                             int t) {
    const int tr = t >> 1;
    const int half = t & 1;
    const float* p = src + (size_t)tr * HEAD_DIM + half * 32;
    float4 f[8];
#pragma unroll
    for (int u = 0; u < 8; u++) f[u] = *(const float4*)(p + 4 * u);
    uint32_t* row = dst + tr * AQ_STR + half * 32;
#pragma unroll
    for (int gg = 0; gg < 4; gg++) {
        float4 lo = f[2 * gg], hi = f[2 * gg + 1];
        *(uint2*)(row + gg * 8 + 0) = make_uint2(to_tf32(lo.x), to_tf32(hi.x));
        *(uint2*)(row + gg * 8 + 2) = make_uint2(to_tf32(lo.y), to_tf32(hi.y));
        *(uint2*)(row + gg * 8 + 4) = make_uint2(to_tf32(lo.z), to_tf32(hi.z));
        *(uint2*)(row + gg * 8 + 6) = make_uint2(to_tf32(lo.w), to_tf32(hi.w));
    }
}

__global__ __launch_bounds__(256, 2) void attn_kernel(const float* __restrict__ sbias)
{
    extern __shared__ uint32_t smu[];
    uint32_t* Qs = smu + OFF_Q;
    uint32_t* Ks = smu + OFF_K;
    uint32_t* Vs = smu + OFF_V;
    float* qcx = (float*)(smu + OFF_QCX);
    float* qcy = (float*)(smu + OFF_QCY);
    float* kcx = (float*)(smu + OFF_KCX);
    float* kcy = (float*)(smu + OFF_KCY);

    const int t    = threadIdx.x;
    const int lane = t & 31;
    const int warp = t >> 5;
    const int q    = lane & 3;
    const int bh = blockIdx.y;
    const int b  = bh / NUM_HEADS, h = bh % NUM_HEADS;
    const int q0 = blockIdx.x * 128;
    const float sb2 = sbias[h] * LOG2E;
    const float sc2 = 0.125f * LOG2E;
    const size_t headbase = (size_t)bh * SEQ * HEAD_DIM;

    const int r0 = warp * 16 + (lane >> 2);
    const int r1 = r0 + 8;

    stage_paired(Qs, g_Q + headbase + (size_t)q0 * HEAD_DIM, t);
    if (t < 128) {
        qcx[t] = g_cx[b * SEQ + q0 + t];
        qcy[t] = g_cy[b * SEQ + q0 + t];
    }
    __syncthreads();

    const float qx0 = qcx[r0], qy0 = qcy[r0];
    const float qx1 = qcx[r1], qy1 = qcy[r1];

    float m0 = -CUDART_INF_F, m1 = -CUDART_INF_F, l0 = 0.f, l1 = 0.f;
    float oacc[8][4];
#pragma unroll
    for (int nt = 0; nt < 8; nt++)
#pragma unroll
        for (int r = 0; r < 4; r++) oacc[nt][r] = 0.f;

    // shuffle sources for c-frag -> a-frag transpose
    const int sA = (lane & ~3) | (q >> 1);
    const int sB = sA + 2;
    const bool qodd = (q & 1) != 0;

    for (int kt = 0; kt < SEQ / 128; kt++) {
        const int k0 = kt * 128;
        __syncthreads();
        stage_paired(Ks, g_K + headbase + (size_t)k0 * HEAD_DIM, t);
        {
            const int tr = t >> 1;
            const int cb = (t & 1) * 32;
            const float* vp = g_V + headbase + (size_t)(k0 + tr) * HEAD_DIM + cb;
            uint32_t* row = Vs + tr * AV_STR + cb;
#pragma unroll
            for (int u = 0; u < 8; u++) {
                float4 v = *(const float4*)(vp + 4 * u);
                *(uint4*)(row + 4 * u) =
                    make_uint4(to_tf32(v.x), to_tf32(v.y), to_tf32(v.z), to_tf32(v.w));
            }
        }
        if (t < 128) {
            kcx[t] = g_cx[b * SEQ + k0 + t];
            kcy[t] = g_cy[b * SEQ + k0 + t];
        }
        __syncthreads();

#pragma unroll
        for (int chunk = 0; chunk < 2; chunk++) {
            const int cbase = chunk * 64;
            // ---- S = Q K^T for this 64-col chunk ----
            float sacc[8][4];
#pragma unroll
            for (int nt = 0; nt < 8; nt++)
                sacc[nt][0] = sacc[nt][1] = sacc[nt][2] = sacc[nt][3] = 0.f;
#pragma unroll
            for (int ks = 0; ks < 8; ks++) {
                uint2 qlo = *(const uint2*)&Qs[r0 * AQ_STR + ks * 8 + 2 * q];
                uint2 qhi = *(const uint2*)&Qs[r1 * AQ_STR + ks * 8 + 2 * q];
#pragma unroll
                for (int nt = 0; nt < 8; nt++) {
                    int col = cbase + nt * 8 + (lane >> 2);
                    uint2 bv = *(const uint2*)&Ks[col * AQ_STR + ks * 8 + 2 * q];
                    mma_tf32(sacc[nt], qlo.x, qhi.x, qlo.y, qhi.y, bv.x, bv.y);
                }
            }

            // ---- bias + scale, row maxima ----
            float pm0 = -CUDART_INF_F, pm1 = -CUDART_INF_F;
#pragma unroll
            for (int nt = 0; nt < 8; nt++) {
                const int c0 = cbase + nt * 8 + 2 * q;
                const float kx0 = kcx[c0], kx1 = kcx[c0 + 1];
                const float ky0 = kcy[c0], ky1 = kcy[c0 + 1];
                float dx, dy;
                dx = qx0 - kx0; dy = qy0 - ky0;
                sacc[nt][0] = sacc[nt][0] * sc2 - sqrtf(dx * dx + dy * dy) * sb2;
                dx = qx0 - kx1; dy = qy0 - ky1;
                sacc[nt][1] = sacc[nt][1] * sc2 - sqrtf(dx * dx + dy * dy) * sb2;
                dx = qx1 - kx0; dy = qy1 - ky0;
                sacc[nt][2] = sacc[nt][2] * sc2 - sqrtf(dx * dx + dy * dy) * sb2;
                dx = qx1 - kx1; dy = qy1 - ky1;
                sacc[nt][3] = sacc[nt][3] * sc2 - sqrtf(dx * dx + dy * dy) * sb2;
                pm0 = fmaxf(pm0, fmaxf(sacc[nt][0], sacc[nt][1]));
                pm1 = fmaxf(pm1, fmaxf(sacc[nt][2], sacc[nt][3]));
            }
            pm0 = fmaxf(pm0, __shfl_xor_sync(0xffffffffu, pm0, 1));
            pm0 = fmaxf(pm0, __shfl_xor_sync(0xffffffffu, pm0, 2));
            pm1 = fmaxf(pm1, __shfl_xor_sync(0xffffffffu, pm1, 1));
            pm1 = fmaxf(pm1, __shfl_xor_sync(0xffffffffu, pm1, 2));

            const float mn0 = fmaxf(m0, pm0), mn1 = fmaxf(m1, pm1);
            const float sc0 = exp2f(m0 - mn0), sc1 = exp2f(m1 - mn1);
            m0 = mn0; m1 = mn1;
#pragma unroll
            for (int nt = 0; nt < 8; nt++) {
                oacc[nt][0] *= sc0; oacc[nt][1] *= sc0;
                oacc[nt][2] *= sc1; oacc[nt][3] *= sc1;
            }

            // ---- p = exp2 (in place), row sums ----
            float s0 = 0.f, s1 = 0.f;
#pragma unroll
            for (int nt = 0; nt < 8; nt++) {
                sacc[nt][0] = exp2f(sacc[nt][0] - mn0);
                sacc[nt][1] = exp2f(sacc[nt][1] - mn0);
                sacc[nt][2] = exp2f(sacc[nt][2] - mn1);
                sacc[nt][3] = exp2f(sacc[nt][3] - mn1);
                s0 += sacc[nt][0] + sacc[nt][1];
                s1 += sacc[nt][2] + sacc[nt][3];
            }
            s0 += __shfl_xor_sync(0xffffffffu, s0, 1);
            s0 += __shfl_xor_sync(0xffffffffu, s0, 2);
            s1 += __shfl_xor_sync(0xffffffffu, s1, 1);
            s1 += __shfl_xor_sync(0xffffffffu, s1, 2);
            l0 = l0 * sc0 + s0;
            l1 = l1 * sc1 + s1;

            // ---- O += P V : c-frag -> a-frag via shuffles, then mma ----
#pragma unroll
            for (int ks = 0; ks < 8; ks++) {
                float u0 = __shfl_sync(0xffffffffu, sacc[ks][0], sA);
                float u1 = __shfl_sync(0xffffffffu, sacc[ks][1], sA);
                float v0 = __shfl_sync(0xffffffffu, sacc[ks][0], sB);
                float v1 = __shfl_sync(0xffffffffu, sacc[ks][1], sB);
                float w0 = __shfl_sync(0xffffffffu, sacc[ks][2], sA);
                float w1 = __shfl_sync(0xffffffffu, sacc[ks][3], sA);
                float x0 = __shfl_sync(0xffffffffu, sacc[ks][2], sB);
                float x1 = __shfl_sync(0xffffffffu, sacc[ks][3], sB);
                uint32_t pa0 = to_tf32(qodd ? u1 : u0);
                uint32_t pa2 = to_tf32(qodd ? v1 : v0);
                uint32_t pa1 = to_tf32(qodd ? w1 : w0);
                uint32_t pa3 = to_tf32(qodd ? x1 : x0);

                const int krow = cbase + ks * 8 + q;
                const uint32_t* vr0 = &Vs[krow * AV_STR + (lane >> 2)];
                const uint32_t* vr1 = &Vs[(krow + 4) * AV_STR + (lane >> 2)];
#pragma unroll
                for (int nt = 0; nt < 8; nt++) {
                    uint32_t vb0 = vr0[nt * 8];
                    uint32_t vb1 = vr1[nt * 8];
                    mma_tf32(oacc[nt], pa0, pa1, pa2, pa3, vb0, vb1);
                }
            }
        }
    }

    // ---- finalize ----
    const float inv0 = 1.f / l0, inv1 = 1.f / l1;
#pragma unroll
    for (int nt = 0; nt < 8; nt++) {
        const int d0 = nt * 8 + 2 * q;
        size_t base0 = ((size_t)(b * SEQ + q0 + r0)) * D_MODEL + h * HEAD_DIM + d0;
        size_t base1 = ((size_t)(b * SEQ + q0 + r1)) * D_MODEL + h * HEAD_DIM + d0;
        *(float2*)(g_att + base0) = make_float2(oacc[nt][0] * inv0, oacc[nt][1] * inv0);
        *(float2*)(g_att + base1) = make_float2(oacc[nt][2] * inv1, oacc[nt][3] * inv1);
    }
}

// ---------------- launch ----------------------------------------------------
extern "C" void kernel_launch(void* const* d_in, const int* in_sizes, int n_in,
                              void* d_out, int out_size)
{
    const float* x     = (const float*)d_in[0];
    const float* boxes = (const float*)d_in[1];
    const float* Wq    = (const float*)d_in[2];
    const float* bq    = (const float*)d_in[3];
    const float* Wk    = (const float*)d_in[4];
    const float* bk    = (const float*)d_in[5];
    const float* Wv    = (const float*)d_in[6];
    const float* bv    = (const float*)d_in[7];
    const float* Wo    = (const float*)d_in[8];
    const float* bo    = (const float*)d_in[9];
    const float* sbias = (const float*)d_in[10];
    float* out = (float*)d_out;

    float *pQ, *pK, *pV, *pAtt;
    cudaGetSymbolAddress((void**)&pQ,   g_Q);
    cudaGetSymbolAddress((void**)&pK,   g_K);
    cudaGetSymbolAddress((void**)&pV,   g_V);
    cudaGetSymbolAddress((void**)&pAtt, g_att);

    cudaFuncSetAttribute(gemm_qkv_kernel,
        cudaFuncAttributeMaxDynamicSharedMemorySize, GEMM_SMEM_BYTES);
    cudaFuncSetAttribute(gemm_out_kernel,
        cudaFuncAttributeMaxDynamicSharedMemorySize, GEMM_SMEM_BYTES);
    cudaFuncSetAttribute(attn_kernel,
        cudaFuncAttributeMaxDynamicSharedMemorySize, ATTN_SMEM_BYTES);

    centers_kernel<<<(NTOK + 255) / 256, 256>>>(boxes);

    dim3 qkvgrid(D_MODEL / 128, NTOK / 128, 3);   // (6, 32, 3)
    gemm_qkv_kernel<<<qkvgrid, 256, GEMM_SMEM_BYTES>>>(
        x, Wq, Wk, Wv, bq, bk, bv, pQ, pK, pV);

    dim3 agrid(SEQ / 128, BATCH * NUM_HEADS);     // (8, 48)
    attn_kernel<<<agrid, 256, ATTN_SMEM_BYTES>>>(sbias);

    dim3 ogrid(D_MODEL / 128, NTOK / 128);        // (6, 32)
    gemm_out_kernel<<<ogrid, 256, GEMM_SMEM_BYTES>>>(pAtt, Wo, bo, out);
}